// round 1
// baseline (speedup 1.0000x reference)
#include <cuda_runtime.h>

#define NMAX  25008
#define FDIM  224
#define NORD  15
#define DV    56
#define TE    128
#define RBP   132   // padded row for rbfT

__device__ float g_q[NMAX * FDIM];
__device__ float g_k[NMAX * FDIM];
__device__ float g_v[NMAX * FDIM];

__device__ __forceinline__ float silu_f(float x) {
    return x / (1.0f + __expf(-x));
}

__global__ void zero_kernel(float* out, int n) {
    int i = blockIdx.x * blockDim.x + threadIdx.x;
    if (i < n) out[i] = 0.0f;
}

// Node precompute: q = silu(Wq@xH), k = silu(Wk@xH), v = Wv@xh
// One thread per output channel c (224). Weight rows live in registers,
// x row staged in smem (warp-uniform broadcast reads).
__global__ __launch_bounds__(224) void node_kernel(
    const float* __restrict__ x, const float* __restrict__ Wq,
    const float* __restrict__ Wk, const float* __restrict__ Wv, int N)
{
    __shared__ float xs[FDIM];
    const int c  = threadIdx.x;
    const int h  = c >> 5;          // head for q/k (DQK=32)
    const int i  = c & 31;
    const int h2 = c / DV;          // head for v (DV=56)
    const int i2 = c - h2 * DV;

    float4 wq[8], wk[8], wv[14];
    const float4* q4 = (const float4*)(Wq + (h * 32 + i) * 32);
    const float4* k4 = (const float4*)(Wk + (h * 32 + i) * 32);
    const float4* v4 = (const float4*)(Wv + (h2 * DV + i2) * DV);
#pragma unroll
    for (int m = 0; m < 8; m++) { wq[m] = q4[m]; wk[m] = k4[m]; }
#pragma unroll
    for (int m = 0; m < 14; m++) wv[m] = v4[m];

    for (int n = blockIdx.x; n < N; n += gridDim.x) {
        __syncthreads();
        xs[c] = x[(size_t)n * FDIM + c];
        __syncthreads();
        float aq = 0.f, ak = 0.f, av = 0.f;
        const float4* xb = (const float4*)(xs + h * 32);
#pragma unroll
        for (int m = 0; m < 8; m++) {
            float4 xv = xb[m];
            aq += wq[m].x * xv.x + wq[m].y * xv.y + wq[m].z * xv.z + wq[m].w * xv.w;
            ak += wk[m].x * xv.x + wk[m].y * xv.y + wk[m].z * xv.z + wk[m].w * xv.w;
        }
        const float4* xb2 = (const float4*)(xs + h2 * DV);
#pragma unroll
        for (int m = 0; m < 14; m++) {
            float4 xv = xb2[m];
            av += wv[m].x * xv.x + wv[m].y * xv.y + wv[m].z * xv.z + wv[m].w * xv.w;
        }
        g_q[(size_t)n * FDIM + c] = silu_f(aq);
        g_k[(size_t)n * FDIM + c] = silu_f(ak);
        g_v[(size_t)n * FDIM + c] = av;
    }
}

// Fused edge kernel: one block per 128 edges.
// smem layout (floats):
//  hT    [224][128]  28672   (layer-1 activations; reused as wT after GEMM2)
//  rbfT  [ 32][132]   4224
//  w2t   [ 16][224]   3584   (streamed W2 chunk)
//  w1r_s [32*112]     3584
//  w1s_s [3*112]       336
//  b1r_s 112, b1s_s 112, b2c_s 224
//  ylm_s [128][15]    1920
//  l0_s  [3][128]      384
//  alp_s [7][128]      896
//  cut_s 128, ii_s 128(int), jj_s 128(int)
__global__ __launch_bounds__(256, 1) void edge_kernel(
    const float* __restrict__ rbf,  const float* __restrict__ ylm,
    const float* __restrict__ cut,  const int* __restrict__ idx_i,
    const int* __restrict__ idx_j,  const float* __restrict__ ev,
    const float* __restrict__ W1r,  const float* __restrict__ b1r,
    const float* __restrict__ W2r,  const float* __restrict__ b2r,
    const float* __restrict__ W1s,  const float* __restrict__ b1s,
    const float* __restrict__ W2s,  const float* __restrict__ b2s,
    float* __restrict__ outx, float* __restrict__ outev,
    int P, int N)
{
    extern __shared__ float sm[];
    float* hT    = sm;               // 28672
    float* rbfT  = hT + 28672;       // 4224
    float* w2t   = rbfT + 4224;      // 3584
    float* w1r_s = w2t + 3584;       // 3584
    float* w1s_s = w1r_s + 3584;     // 336
    float* b1r_s = w1s_s + 336;      // 112
    float* b1s_s = b1r_s + 112;      // 112
    float* b2c_s = b1s_s + 112;      // 224
    float* ylm_s = b2c_s + 224;      // 1920
    float* l0_s  = ylm_s + 1920;     // 384
    float* alp_s = l0_s + 384;       // 896
    float* cut_s = alp_s + 896;      // 128
    int*   ii_s  = (int*)(cut_s + 128);  // 128
    int*   jj_s  = ii_s + 128;           // 128

    const int t  = threadIdx.x;
    const int e0 = blockIdx.x * TE;
    const int nE = min(TE, P - e0);

    // ---- stage 0: loads ----
    if (t < TE) {
        int eg = min(e0 + t, P - 1);
        ii_s[t] = idx_i[eg];
        jj_s[t] = idx_j[eg];
        cut_s[t] = (e0 + t < P) ? cut[e0 + t] : 0.f;
    }
    for (int id = t; id < 3584; id += 256) w1r_s[id] = W1r[id];
    for (int id = t; id < 336;  id += 256) w1s_s[id] = W1s[id];
    if (t < 112) { b1r_s[t] = b1r[t]; b1s_s[t] = b1s[t]; }
    if (t < 224) b2c_s[t] = b2r[t] + b2s[t];
    for (int id = t; id < TE * NORD; id += 256) {
        ylm_s[id] = (e0 + id / NORD < P) ? ylm[(size_t)e0 * NORD + id] : 0.f;
    }
    for (int id = t; id < TE * 32; id += 256) {
        int e = id >> 5, j = id & 31;
        rbfT[j * RBP + e] = (e0 + e < P) ? rbf[(size_t)(e0 + e) * 32 + j] : 0.f;
    }
    __syncthreads();

    // scale rbf by cut; compute l0 contraction
    for (int id = t; id < TE * 32; id += 256) {
        int j = id >> 7, e = id & 127;
        rbfT[j * RBP + e] *= cut_s[e];
    }
    if (t < TE) {
        int a = ii_s[t] * NORD, b = jj_s[t] * NORD;
        float s0 = 0.f, s1 = 0.f, s2 = 0.f;
#pragma unroll
        for (int o = 0; o < NORD; o++) {
            float d = ev[b + o] - ev[a + o];
            float dd = d * d;
            if (o < 3) s0 += dd; else if (o < 8) s1 += dd; else s2 += dd;
        }
        l0_s[t] = s0; l0_s[128 + t] = s1; l0_s[256 + t] = s2;
    }
    __syncthreads();

    // ---- GEMM1: hT[c][e] = silu(layer1) ----
    for (int id = t; id < 224 * TE; id += 256) {
        int c = id >> 7, e = id & 127;
        float acc;
        if (c < 112) {
            acc = b1r_s[c];
#pragma unroll
            for (int j = 0; j < 32; j++) acc += rbfT[j * RBP + e] * w1r_s[j * 112 + c];
        } else {
            int c2 = c - 112;
            acc = b1s_s[c2] + l0_s[e] * w1s_s[c2]
                            + l0_s[128 + e] * w1s_s[112 + c2]
                            + l0_s[256 + e] * w1s_s[224 + c2];
        }
        hT[c * TE + e] = silu_f(acc);
    }
    __syncthreads();

    // ---- GEMM2: w[128][224] = h[128][224] @ W2cat[224][224], reg tile 4x28 ----
    const int tx = t & 31, ty = t >> 5;
    const int ce0 = 4 * tx;    // edge base
    const int cc0 = 28 * ty;   // col base
    float acc[4][28];
#pragma unroll
    for (int i = 0; i < 4; i++)
#pragma unroll
        for (int j = 0; j < 28; j++) acc[i][j] = 0.f;

    for (int kc = 0; kc < 14; kc++) {
        __syncthreads();
#pragma unroll
        for (int it = 0; it < 14; it++) {
            int id = t + 256 * it;
            int kk = id / 224, cc = id - kk * 224;
            int k = kc * 16 + kk;
            const float* src = (k < 112) ? (W2r + k * 224) : (W2s + (k - 112) * 224);
            w2t[id] = src[cc];
        }
        __syncthreads();
#pragma unroll
        for (int kk = 0; kk < 16; kk++) {
            float4 av = *(const float4*)(hT + (kc * 16 + kk) * TE + ce0);
            const float4* brow = (const float4*)(w2t + kk * 224 + cc0);
#pragma unroll
            for (int m = 0; m < 7; m++) {
                float4 bv = brow[m];
                acc[0][4*m+0] += av.x * bv.x; acc[0][4*m+1] += av.x * bv.y;
                acc[0][4*m+2] += av.x * bv.z; acc[0][4*m+3] += av.x * bv.w;
                acc[1][4*m+0] += av.y * bv.x; acc[1][4*m+1] += av.y * bv.y;
                acc[1][4*m+2] += av.y * bv.z; acc[1][4*m+3] += av.y * bv.w;
                acc[2][4*m+0] += av.z * bv.x; acc[2][4*m+1] += av.z * bv.y;
                acc[2][4*m+2] += av.z * bv.z; acc[2][4*m+3] += av.z * bv.w;
                acc[3][4*m+0] += av.w * bv.x; acc[3][4*m+1] += av.w * bv.y;
                acc[3][4*m+2] += av.w * bv.z; acc[3][4*m+3] += av.w * bv.w;
            }
        }
    }
    __syncthreads();   // all hT reads done before overlay write

    // write w (+bias) transposed into hT region: wT[c][e]
#pragma unroll
    for (int j = 0; j < 28; j++) {
        float bb = b2c_s[cc0 + j];
        float4 wv = make_float4(acc[0][j] + bb, acc[1][j] + bb,
                                acc[2][j] + bb, acc[3][j] + bb);
        *(float4*)(hT + (cc0 + j) * TE + ce0) = wv;
    }
    __syncthreads();

    // ---- stage 3: alpha[hh][e] = cut * sum_j q_i*w*k_j ----
    for (int it = 0; it < 4; it++) {
        int task = t + 256 * it;
        if (task < 7 * TE) {
            int hh = task >> 7, e = task & 127;
            int ni = ii_s[e], nj = jj_s[e];
            const float4* qv = (const float4*)(g_q + (size_t)ni * FDIM + hh * 32);
            const float4* kv = (const float4*)(g_k + (size_t)nj * FDIM + hh * 32);
            float s = 0.f;
#pragma unroll
            for (int m = 0; m < 8; m++) {
                float4 q4 = qv[m], k4 = kv[m];
                int wb = (hh * 32 + 4 * m) * TE + e;
                s += q4.x * k4.x * hT[wb];
                s += q4.y * k4.y * hT[wb + TE];
                s += q4.z * k4.z * hT[wb + 2 * TE];
                s += q4.w * k4.w * hT[wb + 3 * TE];
            }
            alp_s[hh * TE + e] = s * cut_s[e];
        }
    }
    __syncthreads();

    // ---- stage 4: segmented scatter (idx_i sorted; atomics at flush) ----
    if (t < FDIM) {
        int hc = t / DV;
        const float* arow = alp_s + hc * TE;
        int icur = ii_s[0];
        float a2 = 0.f;
        for (int e = 0; e < nE; e++) {
            int ie = ii_s[e];
            if (ie != icur) {
                atomicAdd(outx + (size_t)icur * FDIM + t, a2);
                a2 = 0.f; icur = ie;
            }
            a2 += arow[e] * g_v[(size_t)jj_s[e] * FDIM + t];
        }
        atomicAdd(outx + (size_t)icur * FDIM + t, a2);
    } else if (t < FDIM + NORD) {
        int o = t - FDIM;
        int hd = (o < 3) ? 4 : (o < 8) ? 5 : 6;
        const float* arow = alp_s + hd * TE;
        int icur = ii_s[0];
        float a2 = 0.f;
        for (int e = 0; e < nE; e++) {
            int ie = ii_s[e];
            if (ie != icur) {
                atomicAdd(outev + (size_t)icur * NORD + o, a2);
                a2 = 0.f; icur = ie;
            }
            a2 += arow[e] * ylm_s[e * NORD + o];
        }
        atomicAdd(outev + (size_t)icur * NORD + o, a2);
    }
}

extern "C" void kernel_launch(void* const* d_in, const int* in_sizes, int n_in,
                              void* d_out, int out_size)
{
    const float* x    = (const float*)d_in[0];
    const float* ev   = (const float*)d_in[1];
    const float* rbf  = (const float*)d_in[2];
    const float* ylm  = (const float*)d_in[3];
    const float* cutp = (const float*)d_in[4];
    const int*   idxi = (const int*)d_in[5];
    const int*   idxj = (const int*)d_in[6];
    const float* W1r  = (const float*)d_in[7];
    const float* b1r  = (const float*)d_in[8];
    const float* W2r  = (const float*)d_in[9];
    const float* b2r  = (const float*)d_in[10];
    const float* W1s  = (const float*)d_in[11];
    const float* b1s  = (const float*)d_in[12];
    const float* W2s  = (const float*)d_in[13];
    const float* b2s  = (const float*)d_in[14];
    const float* Wq   = (const float*)d_in[15];
    const float* Wk   = (const float*)d_in[16];
    const float* Wv   = (const float*)d_in[17];

    int N = in_sizes[0] / FDIM;
    int P = in_sizes[4];
    float* out   = (float*)d_out;
    float* outx  = out;
    float* outev = out + (size_t)N * FDIM;

    zero_kernel<<<(out_size + 255) / 256, 256>>>(out, out_size);
    node_kernel<<<1024, 224>>>(x, Wq, Wk, Wv, N);

    const int smem_bytes = (28672 + 4224 + 3584 + 3584 + 336 + 112 + 112 + 224 +
                            1920 + 384 + 896 + 128 + 256) * 4;  // 177,728 B
    cudaFuncSetAttribute(edge_kernel,
                         cudaFuncAttributeMaxDynamicSharedMemorySize, smem_bytes);
    int nb = (P + TE - 1) / TE;
    edge_kernel<<<nb, 256, smem_bytes>>>(rbf, ylm, cutp, idxi, idxj, ev,
                                         W1r, b1r, W2r, b2r, W1s, b1s, W2s, b2s,
                                         outx, outev, P, N);
}